// round 3
// baseline (speedup 1.0000x reference)
#include <cuda_runtime.h>
#include <math.h>

#define BB 8
#define LL 2048
#define KSEL 64
#define ROWS 16          // rows per block
#define GRP 8            // rows per group (== warps per block)
#define NBINS 256
#define MAXC 1024        // max candidates per row (avg ~166, worst ~650)
#define THREADS 256
#define NBLK (BB * LL / ROWS)   // 1024

// scratch (no cudaMalloc allowed)
__device__ float g_blocksum[NBLK];
__device__ unsigned int g_done = 0;

// dynamic smem layout
#define SM_PTS_BYTES   (LL * 16)                 // float4 pts        32768
#define SM_CJ_BYTES    (GRP * MAXC * 2)          // ushort cand j     16384
#define SM_HIST_BYTES  (GRP * NBINS * 4)         // per-warp hist      8192
#define SM_DYN_BYTES   (SM_PTS_BYTES + SM_CJ_BYTES + SM_HIST_BYTES)  // 57344

__device__ __forceinline__ float contrib(float d2, float r0) {
    float r = sqrtf(fmaxf(d2, 1e-12f));
    float x = (r0 - r) * (1.0f / 0.3f);                       // (r0-r)/DELTA
    float sp = fmaxf(x, 0.0f) + log1pf(expf(-fabsf(x)));      // stable softplus
    float t = fminf(fmaxf((r - 8.0f) * 0.5f, 0.0f), 1.0f);    // smooth switch
    float sw = 1.0f - t * t * (3.0f - 2.0f * t);
    return 10.0f * sp * sw;                                   // WALL * sp * sw
}

__global__ void __launch_bounds__(THREADS, 3)
main_kernel(const float* __restrict__ R,
            const void*  __restrict__ seq,
            const float* __restrict__ emb,
            const float* __restrict__ wv,
            const float* __restrict__ bp,
            float* __restrict__ out) {
    extern __shared__ char smem[];
    float4*         s_pts  = (float4*)smem;
    unsigned short* s_cj   = (unsigned short*)(smem + SM_PTS_BYTES);
    int*            s_hist = (int*)(smem + SM_PTS_BYTES + SM_CJ_BYTES);

    __shared__ int   s_cnt[GRP];
    __shared__ float s_dotv[20];
    __shared__ float s_bnd_d2[GRP][64];
    __shared__ unsigned short s_bnd_j[GRP][64];
    __shared__ float s_wsum[GRP];
    __shared__ int   s_flag64, s_last;

    const int tid  = threadIdx.x;
    const int lane = tid & 31;
    const int wid  = tid >> 5;
    const int b    = blockIdx.x >> 7;            // 128 blocks per batch
    const int row0 = (blockIdx.x & 127) * ROWS;

    // ---- dot(emb[s], w) + b LUT, int64-vs-int32 seq detection ----
    if (tid == 0) s_flag64 = 1;
    if (tid < 20) {
        float x = bp[0];
#pragma unroll
        for (int d = 0; d < 16; d++) x = fmaf(emb[tid * 16 + d], wv[d], x);
        s_dotv[tid] = x;
    }
    __syncthreads();
    if (tid < 64 && ((const int*)seq)[2 * tid + 1] != 0) s_flag64 = 0;
    __syncthreads();
    const bool is64 = (s_flag64 != 0);

    // ---- stage points + learned radius into shared ----
    const float* Rb = R + (size_t)b * LL * 3;
    for (int j = tid; j < LL; j += THREADS) {
        int s;
        if (is64) s = (int)((const long long*)seq)[(size_t)b * LL + j];
        else      s = ((const int*)seq)[b * LL + j];
        float x = s_dotv[s];
        float rho = 1.6f + 1.2f / (1.0f + expf(-x));
        s_pts[j] = make_float4(Rb[j * 3 + 0], Rb[j * 3 + 1], Rb[j * 3 + 2], rho);
    }
    __syncthreads();

    float lsum = 0.0f;

    for (int g = 0; g < 2; g++) {
        const int i0 = row0 + g * GRP;

        float4 pik[GRP];
#pragma unroll
        for (int k = 0; k < GRP; k++) pik[k] = s_pts[i0 + k];

        if (tid < GRP) s_cnt[tid] = 0;
        __syncthreads();

        // ---- pass 1: distances for 8 rows per point load, compact d2<100 ----
#pragma unroll
        for (int jj = 0; jj < LL / THREADS; jj++) {
            int j = jj * THREADS + tid;
            float4 pj = s_pts[j];
            int base = j - i0;
#pragma unroll
            for (int k = 0; k < GRP; k++) {
                float dx = pik[k].x - pj.x;
                float dy = pik[k].y - pj.y;
                float dz = pik[k].z - pj.z;
                float d2 = fmaf(dx, dx, fmaf(dy, dy, dz * dz));
                bool want = (d2 < 100.0f) && ((unsigned)(base - k + 2) > 4u);
                unsigned msk = __ballot_sync(0xffffffffu, want);
                if (msk) {
                    int ldr = __ffs(msk) - 1;
                    int pos = 0;
                    if (lane == ldr) pos = atomicAdd(&s_cnt[k], __popc(msk));
                    pos = __shfl_sync(0xffffffffu, pos, ldr);
                    if (want) {
                        int my = pos + __popc(msk & ((1u << lane) - 1));
                        if (my < MAXC) s_cj[k * MAXC + my] = (unsigned short)j;
                    }
                }
            }
        }
        __syncthreads();

        // ---- selection: one warp per row, over its candidate list only ----
        {
            const int w = wid;
            const int i = i0 + w;
            const float4 pi = s_pts[i];
            int N = s_cnt[w]; if (N > MAXC) N = MAXC;
            int* hist = s_hist + w * NBINS;

            // zero hist
#pragma unroll
            for (int k = lane; k < NBINS; k += 32) hist[k] = 0;
            __syncwarp();

            // pass A: histogram of d2 (recomputed, bit-identical)
            for (int e = lane; e < N; e += 32) {
                int j = s_cj[w * MAXC + e];
                float4 pj = s_pts[j];
                float dx = pi.x - pj.x, dy = pi.y - pj.y, dz = pi.z - pj.z;
                float d2 = fmaf(dx, dx, fmaf(dy, dy, dz * dz));
                int bin = (int)(d2 * 2.56f); if (bin > 255) bin = 255;
                atomicAdd(&hist[bin], 1);
            }
            __syncwarp();

            // warp scan: threshold bin t, boundary need m
            int loc[8]; int ssum = 0;
#pragma unroll
            for (int k = 0; k < 8; k++) { loc[k] = hist[lane * 8 + k]; ssum += loc[k]; }
            int scan = ssum;
#pragma unroll
            for (int off = 1; off < 32; off <<= 1) {
                int v = __shfl_up_sync(0xffffffffu, scan, off);
                if (lane >= off) scan += v;
            }
            int total  = __shfl_sync(0xffffffffu, scan, 31);
            int before = scan - ssum;
            int tb = NBINS, mm = 0;
            bool own = (total > KSEL) && (before < KSEL) && (scan >= KSEL);
            if (own) {
                int cum = before;
#pragma unroll
                for (int k = 0; k < 8; k++) {
                    if (cum + loc[k] >= KSEL) { tb = lane * 8 + k; mm = KSEL - cum; break; }
                    cum += loc[k];
                }
            }
            unsigned omsk = __ballot_sync(0xffffffffu, own);
            if (omsk) {
                int src = __ffs(omsk) - 1;
                tb = __shfl_sync(0xffffffffu, tb, src);
                mm = __shfl_sync(0xffffffffu, mm, src);
            }

            // pass B: accumulate bins < t, compact boundary (bin == t)
            int Npad = (N + 31) & ~31;
            int bcnt = 0;
            for (int e = lane; e < Npad; e += 32) {
                bool valid = e < N;
                int j = valid ? s_cj[w * MAXC + e] : 0;
                float4 pj = s_pts[j];
                float dx = pi.x - pj.x, dy = pi.y - pj.y, dz = pi.z - pj.z;
                float d2 = fmaf(dx, dx, fmaf(dy, dy, dz * dz));
                int bin = (int)(d2 * 2.56f); if (bin > 255) bin = 255;
                if (valid && bin < tb) lsum += contrib(d2, pi.w + pj.w);
                bool isb = valid && (bin == tb);
                unsigned msk = __ballot_sync(0xffffffffu, isb);
                if (isb) {
                    int pos = bcnt + __popc(msk & ((1u << lane) - 1));
                    if (pos < 64) { s_bnd_d2[w][pos] = d2; s_bnd_j[w][pos] = (unsigned short)j; }
                }
                bcnt += __popc(msk);
            }
            if (bcnt > 64) bcnt = 64;
            __syncwarp();

            // pass C: exact rank-select in the boundary bin (index tiebreak)
            for (int e = lane; e < bcnt; e += 32) {
                float dk = s_bnd_d2[w][e]; int jk = s_bnd_j[w][e];
                int rank = 0;
                for (int l = 0; l < bcnt; l++) {
                    float dl = s_bnd_d2[w][l];
                    rank += (dl < dk) || (dl == dk && s_bnd_j[w][l] < jk);
                }
                if (rank < mm) lsum += contrib(dk, pi.w + s_pts[jk].w);
            }
        }
        __syncthreads();   // before next group resets s_cnt / reuses lists
    }

    // ---- deterministic block reduction (shfl tree, fixed order) ----
#pragma unroll
    for (int off = 16; off; off >>= 1) lsum += __shfl_down_sync(0xffffffffu, lsum, off);
    if (lane == 0) s_wsum[wid] = lsum;
    __syncthreads();
    if (tid == 0) {
        float bs = 0.0f;
#pragma unroll
        for (int w2 = 0; w2 < GRP; w2++) bs += s_wsum[w2];
        g_blocksum[blockIdx.x] = bs;
        __threadfence();
        unsigned t = atomicAdd(&g_done, 1u);
        s_last = (t == NBLK - 1);
    }
    __syncthreads();

    // ---- last block: per-batch reduce in fixed order (deterministic) ----
    if (s_last) {
        __threadfence();
        volatile float* vb = g_blocksum;
        float s = 0.0f;
        for (int e = lane; e < 128; e += 32) s += vb[wid * 128 + e];
#pragma unroll
        for (int off = 16; off; off >>= 1) s += __shfl_down_sync(0xffffffffu, s, off);
        if (lane == 0) out[wid] = s;
        __syncthreads();
        if (tid == 0) g_done = 0;      // reset for next graph replay
    }
}

extern "C" void kernel_launch(void* const* d_in, const int* in_sizes, int n_in,
                              void* d_out, int out_size) {
    const float* R   = (const float*)d_in[0];
    const void*  seq = d_in[1];
    const float* emb = (const float*)d_in[2];
    const float* w   = (const float*)d_in[3];
    const float* bp  = (const float*)d_in[4];
    float* out = (float*)d_out;

    static int attr_set = 0;
    if (!attr_set) {
        cudaFuncSetAttribute(main_kernel,
                             cudaFuncAttributeMaxDynamicSharedMemorySize,
                             SM_DYN_BYTES);
        attr_set = 1;
    }
    main_kernel<<<NBLK, THREADS, SM_DYN_BYTES>>>(R, seq, emb, w, bp, out);
}

// round 4
// speedup vs baseline: 1.3939x; 1.3939x over previous
#include <cuda_runtime.h>
#include <math.h>

#define BB 8
#define LL 2048
#define KSEL 64
#define GRP 8            // rows per group == warps per block
#define NGROUPS 4
#define ROWSB (GRP * NGROUPS)     // 32 rows per block
#define NBINS 256
#define THREADS 256
#define NBLK (BB * LL / ROWSB)    // 512
#define BLKPB (LL / ROWSB)        // 64 blocks per batch

// scratch (no cudaMalloc allowed)
__device__ float g_blocksum[NBLK];
__device__ unsigned int g_done = 0;

// dynamic smem: pts (32KB) + per-row histograms (8KB)
#define SM_PTS_BYTES  (LL * 16)
#define SM_HIST_BYTES (GRP * NBINS * 4)
#define SM_DYN_BYTES  (SM_PTS_BYTES + SM_HIST_BYTES)   // 40960

__device__ __forceinline__ float contrib(float d2, float r0) {
    float r = sqrtf(fmaxf(d2, 1e-12f));
    float x = (r0 - r) * (1.0f / 0.3f);                       // (r0-r)/DELTA
    float sp = fmaxf(x, 0.0f) + log1pf(expf(-fabsf(x)));      // stable softplus
    float t = fminf(fmaxf((r - 8.0f) * 0.5f, 0.0f), 1.0f);    // smooth switch
    float sw = 1.0f - t * t * (3.0f - 2.0f * t);
    return 10.0f * sp * sw;                                   // WALL * sp * sw
}

__global__ void __launch_bounds__(THREADS, 4)
main_kernel(const float* __restrict__ R,
            const void*  __restrict__ seq,
            const float* __restrict__ emb,
            const float* __restrict__ wv,
            const float* __restrict__ bp,
            float* __restrict__ out) {
    extern __shared__ char smem[];
    float4* s_pts  = (float4*)smem;
    int*    s_hist = (int*)(smem + SM_PTS_BYTES);

    __shared__ float s_dotv[20];
    __shared__ int   s_tb[GRP], s_mm[GRP], s_bcnt[GRP];
    __shared__ float s_bnd_d2[GRP][64];
    __shared__ unsigned short s_bnd_j[GRP][64];
    __shared__ float s_wsum[GRP];
    __shared__ int   s_flag64, s_last;

    const int tid  = threadIdx.x;
    const int lane = tid & 31;
    const int wid  = tid >> 5;
    const int b    = blockIdx.x >> 6;           // 64 blocks per batch
    const int row0 = (blockIdx.x & 63) * ROWSB;

    // ---- dot(emb[s], w) + b LUT, int64-vs-int32 seq detection ----
    if (tid == 0) s_flag64 = 1;
    if (tid < 20) {
        float x = bp[0];
#pragma unroll
        for (int d = 0; d < 16; d++) x = fmaf(emb[tid * 16 + d], wv[d], x);
        s_dotv[tid] = x;
    }
    __syncthreads();
    if (tid < 64 && ((const int*)seq)[2 * tid + 1] != 0) s_flag64 = 0;
    __syncthreads();
    const bool is64 = (s_flag64 != 0);

    // ---- stage points + learned radius into shared ----
    const float* Rb = R + (size_t)b * LL * 3;
    for (int j = tid; j < LL; j += THREADS) {
        int s;
        if (is64) s = (int)((const long long*)seq)[(size_t)b * LL + j];
        else      s = ((const int*)seq)[b * LL + j];
        float x = s_dotv[s];
        float rho = 1.6f + 1.2f / (1.0f + expf(-x));
        s_pts[j] = make_float4(Rb[j * 3 + 0], Rb[j * 3 + 1], Rb[j * 3 + 2], rho);
    }

    float lsum = 0.0f;

    for (int g = 0; g < NGROUPS; g++) {
        const int i0 = row0 + g * GRP;

        // zero hists + boundary counters (sync also covers pts load on g==0,
        // and protects previous group's boundary arrays on g>0)
        __syncthreads();
        if (tid < GRP) s_bcnt[tid] = 0;
#pragma unroll
        for (int k = 0; k < SM_HIST_BYTES / 4 / THREADS; k++)
            s_hist[k * THREADS + tid] = 0;
        __syncthreads();

        float4 pik[GRP];
#pragma unroll
        for (int k = 0; k < GRP; k++) pik[k] = s_pts[i0 + k];

        // ---- pass 1: histogram d2<100 for 8 rows per point load ----
#pragma unroll 2
        for (int jj = 0; jj < LL / THREADS; jj++) {
            int j = jj * THREADS + tid;
            float4 pj = s_pts[j];
            bool near = (unsigned)(j - i0 + 2) < 12u;   // j in [i0-2, i0+9]
#pragma unroll
            for (int k = 0; k < GRP; k++) {
                float dx = pik[k].x - pj.x;
                float dy = pik[k].y - pj.y;
                float dz = pik[k].z - pj.z;
                float d2 = fmaf(dx, dx, fmaf(dy, dy, dz * dz));
                if (d2 < 100.0f) {
                    int dd = j - i0 - k;
                    if (!near || dd < -2 || dd > 2) {
                        int bin = (int)(d2 * 2.56f); if (bin > 255) bin = 255;
                        atomicAdd(&s_hist[k * NBINS + bin], 1);
                    }
                }
            }
        }
        __syncthreads();

        // ---- threshold scan: warp w -> row w ----
        {
            int* hist = s_hist + wid * NBINS;
            int loc[8]; int ssum = 0;
#pragma unroll
            for (int k = 0; k < 8; k++) { loc[k] = hist[lane * 8 + k]; ssum += loc[k]; }
            int scan = ssum;
#pragma unroll
            for (int off = 1; off < 32; off <<= 1) {
                int v = __shfl_up_sync(0xffffffffu, scan, off);
                if (lane >= off) scan += v;
            }
            int total  = __shfl_sync(0xffffffffu, scan, 31);
            int before = scan - ssum;
            bool own = (total > KSEL) && (before < KSEL) && (scan >= KSEL);
            int tb = NBINS, mm = 0;
            if (own) {
                int cum = before;
#pragma unroll
                for (int k = 0; k < 8; k++) {
                    if (cum + loc[k] >= KSEL) { tb = lane * 8 + k; mm = KSEL - cum; break; }
                    cum += loc[k];
                }
            }
            unsigned omsk = __ballot_sync(0xffffffffu, own);
            if (omsk) {
                int src = __ffs(omsk) - 1;
                tb = __shfl_sync(0xffffffffu, tb, src);
                mm = __shfl_sync(0xffffffffu, mm, src);
            }
            if (lane == 0) { s_tb[wid] = tb; s_mm[wid] = mm; }
        }
        __syncthreads();

        int tbk[GRP];
#pragma unroll
        for (int k = 0; k < GRP; k++) tbk[k] = s_tb[k];

        // ---- pass 2: recompute d2 (bit-identical), accumulate + boundary ----
#pragma unroll 2
        for (int jj = 0; jj < LL / THREADS; jj++) {
            int j = jj * THREADS + tid;
            float4 pj = s_pts[j];
            bool near = (unsigned)(j - i0 + 2) < 12u;
#pragma unroll
            for (int k = 0; k < GRP; k++) {
                float dx = pik[k].x - pj.x;
                float dy = pik[k].y - pj.y;
                float dz = pik[k].z - pj.z;
                float d2 = fmaf(dx, dx, fmaf(dy, dy, dz * dz));
                if (d2 < 100.0f) {
                    int dd = j - i0 - k;
                    if (!near || dd < -2 || dd > 2) {
                        int bin = (int)(d2 * 2.56f); if (bin > 255) bin = 255;
                        if (bin < tbk[k]) {
                            lsum += contrib(d2, pik[k].w + pj.w);
                        } else if (bin == tbk[k]) {
                            int pos = atomicAdd(&s_bcnt[k], 1);
                            if (pos < 64) {
                                s_bnd_d2[k][pos] = d2;
                                s_bnd_j[k][pos] = (unsigned short)j;
                            }
                        }
                    }
                }
            }
        }
        __syncthreads();

        // ---- boundary rank-select: warp w -> row w (tiny, expected ~1) ----
        {
            int bcnt = s_bcnt[wid]; if (bcnt > 64) bcnt = 64;
            int mm = s_mm[wid];
            float riw = pik[wid].w;   // wrong row's w? no: pik indexed by k == row
            for (int e = lane; e < bcnt; e += 32) {
                float dk = s_bnd_d2[wid][e]; int jk = s_bnd_j[wid][e];
                int rank = 0;
                for (int l = 0; l < bcnt; l++) {
                    float dl = s_bnd_d2[wid][l];
                    rank += (dl < dk) || (dl == dk && s_bnd_j[wid][l] < jk);
                }
                if (rank < mm) lsum += contrib(dk, riw + s_pts[jk].w);
            }
        }
    }

    // ---- deterministic block reduction ----
#pragma unroll
    for (int off = 16; off; off >>= 1) lsum += __shfl_down_sync(0xffffffffu, lsum, off);
    if (lane == 0) s_wsum[wid] = lsum;
    __syncthreads();
    if (tid == 0) {
        float bs = 0.0f;
#pragma unroll
        for (int w2 = 0; w2 < GRP; w2++) bs += s_wsum[w2];
        g_blocksum[blockIdx.x] = bs;
        __threadfence();
        unsigned t = atomicAdd(&g_done, 1u);
        s_last = (t == NBLK - 1);
    }
    __syncthreads();

    // ---- last block: per-batch reduce in fixed order (deterministic) ----
    if (s_last) {
        __threadfence();
        volatile float* vb = g_blocksum;
        float s = vb[wid * BLKPB + lane] + vb[wid * BLKPB + lane + 32];
#pragma unroll
        for (int off = 16; off; off >>= 1) s += __shfl_down_sync(0xffffffffu, s, off);
        if (lane == 0) out[wid] = s;
        __syncthreads();
        if (tid == 0) g_done = 0;    // reset for next graph replay
    }
}

extern "C" void kernel_launch(void* const* d_in, const int* in_sizes, int n_in,
                              void* d_out, int out_size) {
    const float* R   = (const float*)d_in[0];
    const void*  seq = d_in[1];
    const float* emb = (const float*)d_in[2];
    const float* w   = (const float*)d_in[3];
    const float* bp  = (const float*)d_in[4];
    float* out = (float*)d_out;

    static int attr_set = 0;
    if (!attr_set) {
        cudaFuncSetAttribute(main_kernel,
                             cudaFuncAttributeMaxDynamicSharedMemorySize,
                             SM_DYN_BYTES);
        attr_set = 1;
    }
    main_kernel<<<NBLK, THREADS, SM_DYN_BYTES>>>(R, seq, emb, w, bp, out);
}

// round 6
// speedup vs baseline: 2.7541x; 1.9759x over previous
#include <cuda_runtime.h>
#include <math.h>

#define BB 8
#define LL 2048
#define KSEL 64
#define GRP 8            // rows per group == warps per block
#define NGROUPS 4
#define ROWSB (GRP * NGROUPS)     // 32 rows per block
#define NBINS 256
#define THREADS 256
#define NBLK (BB * LL / ROWSB)    // 512
#define BLKPB (LL / ROWSB)        // 64 blocks per batch
#define POOLCAP 4096

// scratch (no cudaMalloc allowed)
__device__ float g_blocksum[NBLK];
__device__ unsigned int g_done = 0;

// dynamic smem: pts (32KB) + candidate pool (8KB) + per-row hist (8KB)
#define SM_PTS_BYTES  (LL * 16)
#define SM_POOL_BYTES (POOLCAP * 2)
#define SM_HIST_BYTES (GRP * NBINS * 4)
#define SM_DYN_BYTES  (SM_PTS_BYTES + SM_POOL_BYTES + SM_HIST_BYTES)  // 49152

__device__ __forceinline__ float dist2(float4 a, float4 b) {
    float dx = a.x - b.x, dy = a.y - b.y, dz = a.z - b.z;
    return fmaf(dx, dx, fmaf(dy, dy, dz * dz));
}

__device__ __forceinline__ float contrib(float d2, float r0) {
    float r = sqrtf(fmaxf(d2, 1e-12f));
    float x = (r0 - r) * (1.0f / 0.3f);                       // (r0-r)/DELTA
    float sp = fmaxf(x, 0.0f) + log1pf(expf(-fabsf(x)));      // stable softplus
    float t = fminf(fmaxf((r - 8.0f) * 0.5f, 0.0f), 1.0f);    // smooth switch
    float sw = 1.0f - t * t * (3.0f - 2.0f * t);
    return 10.0f * sp * sw;                                   // WALL * sp * sw
}

__global__ void __launch_bounds__(THREADS, 4)
main_kernel(const float* __restrict__ R,
            const void*  __restrict__ seq,
            const float* __restrict__ emb,
            const float* __restrict__ wv,
            const float* __restrict__ bp,
            float* __restrict__ out) {
    extern __shared__ char smem[];
    float4*         s_pts  = (float4*)smem;
    unsigned short* s_pool = (unsigned short*)(smem + SM_PTS_BYTES);
    int*            s_hist = (int*)(smem + SM_PTS_BYTES + SM_POOL_BYTES);

    __shared__ float s_dotv[20];
    __shared__ int   s_tb[GRP], s_mm[GRP], s_bcnt[GRP];
    __shared__ float s_bnd_d2[GRP][64];
    __shared__ unsigned short s_bnd_j[GRP][64];
    __shared__ float s_wsum[GRP];
    __shared__ int   s_flag64, s_last, s_poolcnt;

    const int tid  = threadIdx.x;
    const int lane = tid & 31;
    const int wid  = tid >> 5;
    const int b    = blockIdx.x >> 6;           // 64 blocks per batch
    const int row0 = (blockIdx.x & 63) * ROWSB;

    // ---- dot(emb[s], w) + b LUT, int64-vs-int32 seq detection ----
    if (tid == 0) s_flag64 = 1;
    if (tid < 20) {
        float x = bp[0];
#pragma unroll
        for (int d = 0; d < 16; d++) x = fmaf(emb[tid * 16 + d], wv[d], x);
        s_dotv[tid] = x;
    }
    __syncthreads();
    if (tid < 64 && ((const int*)seq)[2 * tid + 1] != 0) s_flag64 = 0;
    __syncthreads();
    const bool is64 = (s_flag64 != 0);

    // ---- stage points + learned radius into shared ----
    const float* Rb = R + (size_t)b * LL * 3;
    for (int j = tid; j < LL; j += THREADS) {
        int s;
        if (is64) s = (int)((const long long*)seq)[(size_t)b * LL + j];
        else      s = ((const int*)seq)[b * LL + j];
        float x = s_dotv[s];
        float rho = 1.6f + 1.2f / (1.0f + expf(-x));
        s_pts[j] = make_float4(Rb[j * 3 + 0], Rb[j * 3 + 1], Rb[j * 3 + 2], rho);
    }

    float lsum = 0.0f;

    for (int g = 0; g < NGROUPS; g++) {
        const int i0 = row0 + g * GRP;

        // protect previous group's pool/hist/bnd; reset counters
        __syncthreads();
        if (tid == 0) s_poolcnt = 0;
        if (tid < GRP) s_bcnt[tid] = 0;
#pragma unroll
        for (int k = 0; k < (GRP * NBINS) / THREADS; k++)
            s_hist[k * THREADS + tid] = 0;
        __syncthreads();

        float4 pik[GRP];
#pragma unroll
        for (int k = 0; k < GRP; k++) pik[k] = s_pts[i0 + k];

        // ---- pass 1: branch-free hit masks, warp-aggregated pool append ----
#pragma unroll
        for (int jj = 0; jj < LL / THREADS; jj++) {
            int j = jj * THREADS + tid;
            float4 pj = s_pts[j];
            int rel = j - i0;
            unsigned mask = 0;
#pragma unroll
            for (int k = 0; k < GRP; k++) {
                float d2 = dist2(pik[k], pj);
                if (d2 < 100.0f) mask |= (1u << k);
            }
            if ((unsigned)(rel + 2) < 12u) {       // rare: bonded-exclusion window
                int lo = rel - 2;
                unsigned m = 0x1Fu;
                if (lo < 0) { m >>= -lo; lo = 0; }
                mask &= ~((m << lo) & 0xFFu);
            }
            int cnt = __popc(mask);
            int scan = cnt;
#pragma unroll
            for (int off = 1; off < 32; off <<= 1) {
                int v = __shfl_up_sync(0xffffffffu, scan, off);
                if (lane >= off) scan += v;
            }
            int base = 0;
            if (lane == 31) base = atomicAdd(&s_poolcnt, scan);
            base = __shfl_sync(0xffffffffu, base, 31) + scan - cnt;
            unsigned mm2 = mask;
            while (mm2) {
                int k = __ffs(mm2) - 1;
                mm2 &= mm2 - 1;
                if (base < POOLCAP)
                    s_pool[base] = (unsigned short)((j << 3) | k);
                base++;
            }
        }
        __syncthreads();

        int cnt_all = s_poolcnt; if (cnt_all > POOLCAP) cnt_all = POOLCAP;

        // ---- histogram over pool (d2 recomputed bit-identically) ----
        for (int e = tid; e < cnt_all; e += THREADS) {
            int rec = s_pool[e];
            int k = rec & 7, j = rec >> 3;
            float d2 = dist2(s_pts[i0 + k], s_pts[j]);
            int bin = (int)(d2 * 2.56f); if (bin > 255) bin = 255;
            atomicAdd(&s_hist[k * NBINS + bin], 1);
        }
        __syncthreads();

        // ---- threshold scan: warp w -> row w ----
        {
            int* hist = s_hist + wid * NBINS;
            int loc[8]; int ssum = 0;
#pragma unroll
            for (int k = 0; k < 8; k++) { loc[k] = hist[lane * 8 + k]; ssum += loc[k]; }
            int scan = ssum;
#pragma unroll
            for (int off = 1; off < 32; off <<= 1) {
                int v = __shfl_up_sync(0xffffffffu, scan, off);
                if (lane >= off) scan += v;
            }
            int total  = __shfl_sync(0xffffffffu, scan, 31);
            int before = scan - ssum;
            bool own = (total > KSEL) && (before < KSEL) && (scan >= KSEL);
            int tb = NBINS, mm = 0;
            if (own) {
                int cum = before;
#pragma unroll
                for (int k = 0; k < 8; k++) {
                    if (cum + loc[k] >= KSEL) { tb = lane * 8 + k; mm = KSEL - cum; break; }
                    cum += loc[k];
                }
            }
            unsigned omsk = __ballot_sync(0xffffffffu, own);
            if (omsk) {
                int src = __ffs(omsk) - 1;
                tb = __shfl_sync(0xffffffffu, tb, src);
                mm = __shfl_sync(0xffffffffu, mm, src);
            }
            if (lane == 0) { s_tb[wid] = tb; s_mm[wid] = mm; }
        }
        __syncthreads();

        // ---- accumulate over pool; collect boundary candidates ----
        for (int e = tid; e < cnt_all; e += THREADS) {
            int rec = s_pool[e];
            int k = rec & 7, j = rec >> 3;
            float4 pi = s_pts[i0 + k];
            float4 pj = s_pts[j];
            float d2 = dist2(pi, pj);
            int bin = (int)(d2 * 2.56f); if (bin > 255) bin = 255;
            int tb = s_tb[k];
            if (bin < tb) {
                lsum += contrib(d2, pi.w + pj.w);
            } else if (bin == tb) {
                int pos = atomicAdd(&s_bcnt[k], 1);
                if (pos < 64) {
                    s_bnd_d2[k][pos] = d2;
                    s_bnd_j[k][pos] = (unsigned short)j;
                }
            }
        }
        __syncthreads();

        // ---- boundary rank-select: warp w -> row w (tiny) ----
        {
            int bcnt = s_bcnt[wid]; if (bcnt > 64) bcnt = 64;
            int mm = s_mm[wid];
            float riw = pik[wid].w;
            for (int e = lane; e < bcnt; e += 32) {
                float dk = s_bnd_d2[wid][e]; int jk = s_bnd_j[wid][e];
                int rank = 0;
                for (int l = 0; l < bcnt; l++) {
                    float dl = s_bnd_d2[wid][l];
                    rank += (dl < dk) || (dl == dk && s_bnd_j[wid][l] < jk);
                }
                if (rank < mm) lsum += contrib(dk, riw + s_pts[jk].w);
            }
        }
    }

    // ---- deterministic block reduction ----
#pragma unroll
    for (int off = 16; off; off >>= 1) lsum += __shfl_down_sync(0xffffffffu, lsum, off);
    if (lane == 0) s_wsum[wid] = lsum;
    __syncthreads();
    if (tid == 0) {
        float bs = 0.0f;
#pragma unroll
        for (int w2 = 0; w2 < GRP; w2++) bs += s_wsum[w2];
        g_blocksum[blockIdx.x] = bs;
        __threadfence();
        unsigned t = atomicAdd(&g_done, 1u);
        s_last = (t == NBLK - 1);
    }
    __syncthreads();

    // ---- last block: per-batch reduce in fixed order ----
    if (s_last) {
        __threadfence();
        volatile float* vb = g_blocksum;
        float s = vb[wid * BLKPB + lane] + vb[wid * BLKPB + lane + 32];
#pragma unroll
        for (int off = 16; off; off >>= 1) s += __shfl_down_sync(0xffffffffu, s, off);
        if (lane == 0) out[wid] = s;
        __syncthreads();
        if (tid == 0) g_done = 0;    // reset for next graph replay
    }
}

extern "C" void kernel_launch(void* const* d_in, const int* in_sizes, int n_in,
                              void* d_out, int out_size) {
    const float* R   = (const float*)d_in[0];
    const void*  seq = d_in[1];
    const float* emb = (const float*)d_in[2];
    const float* w   = (const float*)d_in[3];
    const float* bp  = (const float*)d_in[4];
    float* out = (float*)d_out;

    static int attr_set = 0;
    if (!attr_set) {
        cudaFuncSetAttribute(main_kernel,
                             cudaFuncAttributeMaxDynamicSharedMemorySize,
                             SM_DYN_BYTES);
        attr_set = 1;
    }
    main_kernel<<<NBLK, THREADS, SM_DYN_BYTES>>>(R, seq, emb, w, bp, out);
}

// round 8
// speedup vs baseline: 3.2734x; 1.1885x over previous
#include <cuda_runtime.h>
#include <math.h>

#define BB 8
#define LL 2048
#define KSEL 64
#define GRP 8            // rows per group == warps per block
#define NGROUPS 4
#define ROWSB (GRP * NGROUPS)     // 32 rows per block
#define NBINS 256
#define THREADS 256
#define NBLK (BB * LL / ROWSB)    // 512
#define BLKPB (LL / ROWSB)        // 64 blocks per batch
#define POOLCAP 4096

// scratch (no cudaMalloc allowed)
__device__ float g_blocksum[NBLK];
__device__ unsigned int g_done = 0;

// dynamic smem: pts (32KB) + candidate pool (8KB) + per-row hist (8KB)
#define SM_PTS_BYTES  (LL * 16)
#define SM_POOL_BYTES (POOLCAP * 2)
#define SM_HIST_BYTES (GRP * NBINS * 4)
#define SM_DYN_BYTES  (SM_PTS_BYTES + SM_POOL_BYTES + SM_HIST_BYTES)  // 49152

typedef unsigned long long u64;

__device__ __forceinline__ u64 pack2(float lo, float hi) {
    u64 r; asm("mov.b64 %0,{%1,%2};" : "=l"(r) : "f"(lo), "f"(hi)); return r;
}
__device__ __forceinline__ u64 add2(u64 a, u64 b) {
    u64 r; asm("add.rn.f32x2 %0,%1,%2;" : "=l"(r) : "l"(a), "l"(b)); return r;
}
__device__ __forceinline__ u64 fma2(u64 a, u64 b, u64 c) {
    u64 r; asm("fma.rn.f32x2 %0,%1,%2,%3;" : "=l"(r) : "l"(a), "l"(b), "l"(c)); return r;
}
__device__ __forceinline__ void unpack2(u64 v, unsigned &lo, unsigned &hi) {
    asm("mov.b64 {%0,%1},%2;" : "=r"(lo), "=r"(hi) : "l"(v));
}

__device__ __forceinline__ float dist2(float4 a, float4 b) {
    float dx = a.x - b.x, dy = a.y - b.y, dz = a.z - b.z;
    return fmaf(dx, dx, fmaf(dy, dy, dz * dz));
}

__device__ __forceinline__ float contrib(float d2, float r0) {
    float r = sqrtf(fmaxf(d2, 1e-12f));
    float x = (r0 - r) * (1.0f / 0.3f);                       // (r0-r)/DELTA
    float sp = fmaxf(x, 0.0f) + log1pf(expf(-fabsf(x)));      // stable softplus
    float t = fminf(fmaxf((r - 8.0f) * 0.5f, 0.0f), 1.0f);    // smooth switch
    float sw = 1.0f - t * t * (3.0f - 2.0f * t);
    return 10.0f * sp * sw;                                   // WALL * sp * sw
}

__global__ void __launch_bounds__(THREADS, 4)
main_kernel(const float* __restrict__ R,
            const void*  __restrict__ seq,
            const float* __restrict__ emb,
            const float* __restrict__ wv,
            const float* __restrict__ bp,
            float* __restrict__ out) {
    extern __shared__ char smem[];
    float4*         s_pts  = (float4*)smem;
    unsigned short* s_pool = (unsigned short*)(smem + SM_PTS_BYTES);
    int*            s_hist = (int*)(smem + SM_PTS_BYTES + SM_POOL_BYTES);

    __shared__ float s_dotv[20];
    __shared__ int   s_tb[GRP], s_mm[GRP], s_bcnt[GRP];
    __shared__ float s_bnd_d2[GRP][64];
    __shared__ unsigned short s_bnd_j[GRP][64];
    __shared__ float s_wsum[GRP];
    __shared__ int   s_flag64, s_last, s_poolcnt;

    const int tid  = threadIdx.x;
    const int lane = tid & 31;
    const int wid  = tid >> 5;
    const int b    = blockIdx.x >> 6;           // 64 blocks per batch
    const int row0 = (blockIdx.x & 63) * ROWSB;

    // ---- dot(emb[s], w) + b LUT, int64-vs-int32 seq detection ----
    if (tid == 0) s_flag64 = 1;
    if (tid < 20) {
        float x = bp[0];
#pragma unroll
        for (int d = 0; d < 16; d++) x = fmaf(emb[tid * 16 + d], wv[d], x);
        s_dotv[tid] = x;
    }
    __syncthreads();
    if (tid < 64 && ((const int*)seq)[2 * tid + 1] != 0) s_flag64 = 0;
    __syncthreads();
    const bool is64 = (s_flag64 != 0);

    // ---- stage points + learned radius into shared ----
    const float* Rb = R + (size_t)b * LL * 3;
    for (int j = tid; j < LL; j += THREADS) {
        int s;
        if (is64) s = (int)((const long long*)seq)[(size_t)b * LL + j];
        else      s = ((const int*)seq)[b * LL + j];
        float x = s_dotv[s];
        float rho = 1.6f + 1.2f / (1.0f + expf(-x));
        s_pts[j] = make_float4(Rb[j * 3 + 0], Rb[j * 3 + 1], Rb[j * 3 + 2], rho);
    }

    float lsum = 0.0f;
    const u64 C100 = pack2(-100.0f, -100.0f);

    for (int g = 0; g < NGROUPS; g++) {
        const int i0 = row0 + g * GRP;

        // protect previous group's pool/hist/bnd; reset counters
        __syncthreads();
        if (tid == 0) s_poolcnt = 0;
        if (tid < GRP) s_bcnt[tid] = 0;
#pragma unroll
        for (int k = 0; k < (GRP * NBINS) / THREADS; k++)
            s_hist[k * THREADS + tid] = 0;
        __syncthreads();

        // negated row-pair broadcasts: lane lo = row 2rp, lane hi = row 2rp+1
        u64 nx2[4], ny2[4], nz2[4];
#pragma unroll
        for (int rp = 0; rp < 4; rp++) {
            float4 a  = s_pts[i0 + 2 * rp];
            float4 b2 = s_pts[i0 + 2 * rp + 1];
            nx2[rp] = pack2(-a.x, -b2.x);
            ny2[rp] = pack2(-a.y, -b2.y);
            nz2[rp] = pack2(-a.z, -b2.z);
        }

        // ---- pass 1: packed f32x2 distances, sign-bit filter, pool append ----
#pragma unroll
        for (int jj = 0; jj < LL / (2 * THREADS); jj++) {
            int j  = jj * (2 * THREADS) + tid;
            int j2 = j + THREADS;
            float4 p1 = s_pts[j];
            float4 p2 = s_pts[j2];
            u64 p1x = pack2(p1.x, p1.x), p1y = pack2(p1.y, p1.y), p1z = pack2(p1.z, p1.z);
            u64 p2x = pack2(p2.x, p2.x), p2y = pack2(p2.y, p2.y), p2z = pack2(p2.z, p2.z);
            unsigned mask = 0;
#pragma unroll
            for (int rp = 0; rp < 4; rp++) {
                u64 dx = add2(p1x, nx2[rp]);
                u64 dy = add2(p1y, ny2[rp]);
                u64 dz = add2(p1z, nz2[rp]);
                u64 t  = fma2(dz, dz, C100);
                t = fma2(dy, dy, t);
                t = fma2(dx, dx, t);               // d2 - 100 per half
                unsigned lo, hi; unpack2(t, lo, hi);
                mask |= (lo >> 31) << (2 * rp);
                mask |= (hi >> 31) << (2 * rp + 1);

                dx = add2(p2x, nx2[rp]);
                dy = add2(p2y, ny2[rp]);
                dz = add2(p2z, nz2[rp]);
                t  = fma2(dz, dz, C100);
                t = fma2(dy, dy, t);
                t = fma2(dx, dx, t);
                unpack2(t, lo, hi);
                mask |= (lo >> 31) << (8 + 2 * rp);
                mask |= (hi >> 31) << (8 + 2 * rp + 1);
            }
            // bonded-exclusion windows (rare)
            int rel = j - i0;
            if ((unsigned)(rel + 2) < 12u) {
                int lo = rel - 2; unsigned m = 0x1Fu;
                if (lo < 0) { m >>= -lo; lo = 0; }
                mask &= ~((m << lo) & 0xFFu);
            }
            int rel2 = j2 - i0;
            if ((unsigned)(rel2 + 2) < 12u) {
                int lo = rel2 - 2; unsigned m = 0x1Fu;
                if (lo < 0) { m >>= -lo; lo = 0; }
                mask &= ~(((m << lo) & 0xFFu) << 8);
            }

            int cnt = __popc(mask);
            int scan = cnt;
#pragma unroll
            for (int off = 1; off < 32; off <<= 1) {
                int v = __shfl_up_sync(0xffffffffu, scan, off);
                if (lane >= off) scan += v;
            }
            int base = 0;
            if (lane == 31) base = atomicAdd(&s_poolcnt, scan);
            base = __shfl_sync(0xffffffffu, base, 31) + scan - cnt;
            unsigned mm2 = mask;
            while (mm2) {
                int bpos = __ffs(mm2) - 1;
                mm2 &= mm2 - 1;
                int k  = bpos & 7;
                int jx = (bpos & 8) ? j2 : j;
                if (base < POOLCAP)
                    s_pool[base] = (unsigned short)((jx << 3) | k);
                base++;
            }
        }
        __syncthreads();

        int cnt_all = s_poolcnt; if (cnt_all > POOLCAP) cnt_all = POOLCAP;

        // ---- histogram over pool (plain scalar d2, consistent within pool) ----
        for (int e = tid; e < cnt_all; e += THREADS) {
            int rec = s_pool[e];
            int k = rec & 7, j = rec >> 3;
            float d2 = dist2(s_pts[i0 + k], s_pts[j]);
            int bin = (int)(d2 * 2.56f); if (bin > 255) bin = 255;
            atomicAdd(&s_hist[k * NBINS + bin], 1);
        }
        __syncthreads();

        // ---- threshold scan: warp w -> row w ----
        {
            int* hist = s_hist + wid * NBINS;
            int loc[8]; int ssum = 0;
#pragma unroll
            for (int k = 0; k < 8; k++) { loc[k] = hist[lane * 8 + k]; ssum += loc[k]; }
            int scan = ssum;
#pragma unroll
            for (int off = 1; off < 32; off <<= 1) {
                int v = __shfl_up_sync(0xffffffffu, scan, off);
                if (lane >= off) scan += v;
            }
            int total  = __shfl_sync(0xffffffffu, scan, 31);
            int before = scan - ssum;
            bool own = (total > KSEL) && (before < KSEL) && (scan >= KSEL);
            int tb = NBINS, mm = 0;
            if (own) {
                int cum = before;
#pragma unroll
                for (int k = 0; k < 8; k++) {
                    if (cum + loc[k] >= KSEL) { tb = lane * 8 + k; mm = KSEL - cum; break; }
                    cum += loc[k];
                }
            }
            unsigned omsk = __ballot_sync(0xffffffffu, own);
            if (omsk) {
                int src = __ffs(omsk) - 1;
                tb = __shfl_sync(0xffffffffu, tb, src);
                mm = __shfl_sync(0xffffffffu, mm, src);
            }
            if (lane == 0) { s_tb[wid] = tb; s_mm[wid] = mm; }
        }
        __syncthreads();

        // ---- accumulate over pool; collect boundary candidates ----
        for (int e = tid; e < cnt_all; e += THREADS) {
            int rec = s_pool[e];
            int k = rec & 7, j = rec >> 3;
            float4 pi = s_pts[i0 + k];
            float4 pj = s_pts[j];
            float d2 = dist2(pi, pj);
            int bin = (int)(d2 * 2.56f); if (bin > 255) bin = 255;
            int tb = s_tb[k];
            if (bin < tb) {
                lsum += contrib(d2, pi.w + pj.w);
            } else if (bin == tb) {
                int pos = atomicAdd(&s_bcnt[k], 1);
                if (pos < 64) {
                    s_bnd_d2[k][pos] = d2;
                    s_bnd_j[k][pos] = (unsigned short)j;
                }
            }
        }
        __syncthreads();

        // ---- boundary rank-select: warp w -> row w (tiny) ----
        {
            int bcnt = s_bcnt[wid]; if (bcnt > 64) bcnt = 64;
            int mm = s_mm[wid];
            float riw = s_pts[i0 + wid].w;
            for (int e = lane; e < bcnt; e += 32) {
                float dk = s_bnd_d2[wid][e]; int jk = s_bnd_j[wid][e];
                int rank = 0;
                for (int l = 0; l < bcnt; l++) {
                    float dl = s_bnd_d2[wid][l];
                    rank += (dl < dk) || (dl == dk && s_bnd_j[wid][l] < jk);
                }
                if (rank < mm) lsum += contrib(dk, riw + s_pts[jk].w);
            }
        }
    }

    // ---- deterministic block reduction ----
#pragma unroll
    for (int off = 16; off; off >>= 1) lsum += __shfl_down_sync(0xffffffffu, lsum, off);
    if (lane == 0) s_wsum[wid] = lsum;
    __syncthreads();
    if (tid == 0) {
        float bs = 0.0f;
#pragma unroll
        for (int w2 = 0; w2 < GRP; w2++) bs += s_wsum[w2];
        g_blocksum[blockIdx.x] = bs;
        __threadfence();
        unsigned t = atomicAdd(&g_done, 1u);
        s_last = (t == NBLK - 1);
    }
    __syncthreads();

    // ---- last block: per-batch reduce in fixed order ----
    if (s_last) {
        __threadfence();
        volatile float* vb = g_blocksum;
        float s = vb[wid * BLKPB + lane] + vb[wid * BLKPB + lane + 32];
#pragma unroll
        for (int off = 16; off; off >>= 1) s += __shfl_down_sync(0xffffffffu, s, off);
        if (lane == 0) out[wid] = s;
        __syncthreads();
        if (tid == 0) g_done = 0;    // reset for next graph replay
    }
}

extern "C" void kernel_launch(void* const* d_in, const int* in_sizes, int n_in,
                              void* d_out, int out_size) {
    const float* R   = (const float*)d_in[0];
    const void*  seq = d_in[1];
    const float* emb = (const float*)d_in[2];
    const float* w   = (const float*)d_in[3];
    const float* bp  = (const float*)d_in[4];
    float* out = (float*)d_out;

    static int attr_set = 0;
    if (!attr_set) {
        cudaFuncSetAttribute(main_kernel,
                             cudaFuncAttributeMaxDynamicSharedMemorySize,
                             SM_DYN_BYTES);
        attr_set = 1;
    }
    main_kernel<<<NBLK, THREADS, SM_DYN_BYTES>>>(R, seq, emb, w, bp, out);
}